// round 4
// baseline (speedup 1.0000x reference)
#include <cuda_runtime.h>
#include <cstdint>

// Problem constants
#define Bn 16
#define Cn 256
#define Hn 128
#define Wn 128
#define HW (Hn*Wn)            // 16384 = 2^14
#define CHW (Cn*HW)           // 4194304 = 2^22
#define CHW4 (CHW/4)          // 1048576 = 2^20
#define HW4 (HW/4)            // 4096

// Chunking: 2 batches per chunk -> 32 MiB of x; K3 footprint ~66MB << 126MB L2
#define BCHUNK 2
#define NCHUNK (Bn/BCHUNK)    // 8
#define CGROUPS 16            // split-C groups in reduce (MLP=16/thread)
#define CPER (Cn/CGROUPS)     // 16 channels per group
#define CHUNK_PIX (BCHUNK*HW)    // 32768 pixels per chunk
#define CHUNK_PIX4 (CHUNK_PIX/4) // 8192

// Scratch (__device__ globals; reused serially across chunks)
__device__ float g_part[CGROUPS * CHUNK_PIX]; // 2 MiB partial channel sums
__device__ float g_x1[CHUNK_PIX];             // 128 KiB conv result

// ---------------------------------------------------------------------------
// K1: partial channel sums for one chunk.
// 131072 threads (512 blocks x 256); thread i: group g = i>>13, j = i&8191.
// part4[i] = sum over 16 channels of x[bl, g*16+c, hw4]  (16 LDG.128 in flight)
// ---------------------------------------------------------------------------
__global__ void __launch_bounds__(256) reduce_part_kernel(const float4* __restrict__ x,
                                                          float4* __restrict__ part4) {
    int i = blockIdx.x * blockDim.x + threadIdx.x;  // 0 .. 131071
    int g = i >> 13;            // 0..15
    int j = i & 8191;           // chunk pixel (float4)
    int bl  = j >> 12;          // 0..1 batch-in-chunk
    int hw4 = j & 4095;

    const float4* p = x + (size_t)bl * CHW4 + (size_t)g * CPER * HW4 + hw4;

    float4 acc = make_float4(0.f, 0.f, 0.f, 0.f);
#pragma unroll 16
    for (int c = 0; c < CPER; ++c) {
        float4 v = p[(size_t)c * HW4];
        acc.x += v.x; acc.y += v.y; acc.z += v.z; acc.w += v.w;
    }
    part4[i] = acc;
}

// ---------------------------------------------------------------------------
// K2: combine partials + 3x3 conv (cross-correlation, zero pad) in one pass.
// 32768 threads, one per chunk pixel. All loads L2/L1-resident (2.1 MiB).
// ---------------------------------------------------------------------------
__global__ void __launch_bounds__(256) conv_combine_kernel(const float* __restrict__ part,
                                                           const float* __restrict__ f,
                                                           float* __restrict__ x1) {
    int i = blockIdx.x * blockDim.x + threadIdx.x;  // 0 .. 32767
    int bl = i >> 14;
    int hw = i & (HW - 1);
    int h  = hw >> 7;
    int w  = hw & (Wn - 1);

    float fw[9];
#pragma unroll
    for (int k = 0; k < 9; ++k) fw[k] = f[k];

    int base = bl * HW;
    float acc = 0.f;
#pragma unroll
    for (int di = 0; di < 3; ++di) {
        int hh = h + di - 1;
        if (hh < 0 || hh >= Hn) continue;
#pragma unroll
        for (int dj = 0; dj < 3; ++dj) {
            int ww = w + dj - 1;
            if (ww < 0 || ww >= Wn) continue;
            int pos = base + hh * Wn + ww;
            float sv = 0.f;
#pragma unroll
            for (int g = 0; g < CGROUPS; ++g)
                sv += part[g * CHUNK_PIX + pos];
            acc += sv * fw[di * 3 + dj];
        }
    }
    x1[i] = acc;
}

// ---------------------------------------------------------------------------
// K3: out = x - x1 (broadcast over C) for one chunk.
// x reads should hit L2 (loaded by K1, 32MiB chunk); out stored evict-first.
// 2097152 float4 elements per chunk.
// ---------------------------------------------------------------------------
__global__ void __launch_bounds__(256) sub_kernel(const float4* __restrict__ x,
                                                  const float4* __restrict__ x1,
                                                  float4* __restrict__ out) {
    int i = blockIdx.x * blockDim.x + threadIdx.x;  // 0 .. 2097151
    int bl  = i >> 20;          // batch-in-chunk (CHW4 = 2^20)
    int hw4 = i & 4095;
    float4 xv = x[i];
    float4 bv = __ldg(&x1[(bl << 12) + hw4]);
    float4 o;
    o.x = xv.x - bv.x;
    o.y = xv.y - bv.y;
    o.z = xv.z - bv.z;
    o.w = xv.w - bv.w;
    __stcs(&out[i], o);
}

// ---------------------------------------------------------------------------
extern "C" void kernel_launch(void* const* d_in, const int* in_sizes, int n_in,
                              void* d_out, int out_size) {
    const float* x = (const float*)d_in[0];   // (16,256,128,128) fp32
    const float* f = (const float*)d_in[1];   // (3,3) fp32
    float* out = (float*)d_out;

    static float* part_ptr = nullptr;
    static float* x1_ptr   = nullptr;
    if (part_ptr == nullptr) {
        cudaGetSymbolAddress((void**)&part_ptr, g_part);
        cudaGetSymbolAddress((void**)&x1_ptr,   g_x1);
    }

    for (int c = 0; c < NCHUNK; ++c) {
        const float4* xc = (const float4*)x   + (size_t)c * BCHUNK * CHW4;
        float4*       oc = (float4*)out       + (size_t)c * BCHUNK * CHW4;

        // K1: partial channel sums (reads 32 MiB DRAM, warms L2 with x chunk)
        reduce_part_kernel<<<(CGROUPS * CHUNK_PIX4) / 256, 256>>>(
            xc, (float4*)part_ptr);

        // K2: combine + conv (tiny, L2-resident)
        conv_combine_kernel<<<CHUNK_PIX / 256, 256>>>(part_ptr, f, x1_ptr);

        // K3: broadcast subtract (x reads from L2, out writes evict-first)
        sub_kernel<<<(BCHUNK * CHW4) / 256, 256>>>(
            xc, (const float4*)x1_ptr, oc);
    }
}

// round 5
// speedup vs baseline: 1.2562x; 1.2562x over previous
#include <cuda_runtime.h>
#include <cstdint>

// Problem constants
#define Bn 16
#define Cn 256
#define Hn 128
#define Wn 128
#define HW (Hn*Wn)            // 16384 = 2^14
#define HW4 (HW/4)            // 4096
#define CHW (Cn*HW)           // 4194304
#define CHW4 (CHW/4)          // 1048576 = 2^20
#define BHW (Bn*HW)           // 262144
#define BHW4 (BHW/4)          // 65536
#define TOTAL4 (Bn*CHW4)      // 16777216

#define CGROUPS 8
#define CPER (Cn/CGROUPS)     // 32 channels per group

// Scratch (__device__ globals)
__device__ float g_part[CGROUPS * BHW];  // 8 MiB partial channel sums
__device__ float g_s[BHW];               // 1 MiB channel sum
__device__ float g_x1[BHW];              // 1 MiB conv result

// ---------------------------------------------------------------------------
// K1: partial channel sums, monolithic. 524288 threads (2048 blocks x 256).
// thread i: group g = i>>16, j = i&65535 (global float4 pixel: b = j>>12).
// part4[g*BHW4 + j] = sum over 32 channels of x[b, g*32+c, hw4]
// ---------------------------------------------------------------------------
__global__ void __launch_bounds__(256) reduce_part_kernel(const float4* __restrict__ x,
                                                          float4* __restrict__ part4) {
    int i = blockIdx.x * blockDim.x + threadIdx.x;  // 0 .. 524287
    int g = i >> 16;            // 0..7
    int j = i & 65535;          // global pixel (float4)
    int b   = j >> 12;          // batch
    int hw4 = j & 4095;

    const float4* p = x + (size_t)b * CHW4 + (size_t)g * CPER * HW4 + hw4;

    float4 acc = make_float4(0.f, 0.f, 0.f, 0.f);
#pragma unroll 8
    for (int c = 0; c < CPER; ++c) {
        float4 v = p[(size_t)c * HW4];
        acc.x += v.x; acc.y += v.y; acc.z += v.z; acc.w += v.w;
    }
    part4[(size_t)g * BHW4 + j] = acc;
}

// ---------------------------------------------------------------------------
// K2a: combine 8 partials -> s.  65536 float4 threads. 8 MiB read (L2), 1 MiB write.
// ---------------------------------------------------------------------------
__global__ void __launch_bounds__(256) combine_kernel(const float4* __restrict__ part4,
                                                      float4* __restrict__ s4) {
    int j = blockIdx.x * blockDim.x + threadIdx.x;  // 0 .. 65535
    float4 acc = make_float4(0.f, 0.f, 0.f, 0.f);
#pragma unroll
    for (int g = 0; g < CGROUPS; ++g) {
        float4 v = part4[(size_t)g * BHW4 + j];
        acc.x += v.x; acc.y += v.y; acc.z += v.z; acc.w += v.w;
    }
    s4[j] = acc;
}

// ---------------------------------------------------------------------------
// K2b: x1 = conv3x3(s), zero pad, cross-correlation. 262144 threads, L2-resident.
// ---------------------------------------------------------------------------
__global__ void __launch_bounds__(256) conv3_kernel(const float* __restrict__ s,
                                                    const float* __restrict__ f,
                                                    float* __restrict__ x1) {
    int i = blockIdx.x * blockDim.x + threadIdx.x;  // 0 .. BHW-1
    int b  = i >> 14;
    int hw = i & (HW - 1);
    int h  = hw >> 7;
    int w  = hw & (Wn - 1);

    float fw[9];
#pragma unroll
    for (int k = 0; k < 9; ++k) fw[k] = f[k];

    const float* sb = s + b * HW;
    float acc = 0.f;
#pragma unroll
    for (int di = 0; di < 3; ++di) {
        int hh = h + di - 1;
        if (hh < 0 || hh >= Hn) continue;
#pragma unroll
        for (int dj = 0; dj < 3; ++dj) {
            int ww = w + dj - 1;
            if (ww < 0 || ww >= Wn) continue;
            acc += sb[hh * Wn + ww] * fw[di * 3 + dj];
        }
    }
    x1[i] = acc;
}

// ---------------------------------------------------------------------------
// K3: out = x - x1 (broadcast over C), ILP=2. 8388608 threads, each handles
// float4 elements i and i+TOTAL4/2 (both fully coalesced streams).
// ---------------------------------------------------------------------------
__global__ void __launch_bounds__(256) sub_kernel(const float4* __restrict__ x,
                                                  const float4* __restrict__ x1,
                                                  float4* __restrict__ out) {
    int i = blockIdx.x * blockDim.x + threadIdx.x;  // 0 .. 8388607
    int i2 = i + (TOTAL4 / 2);

    float4 xa = x[i];
    float4 xb = x[i2];
    float4 ba = __ldg(&x1[((i  >> 20) << 12) + (i  & 4095)]);
    float4 bb = __ldg(&x1[((i2 >> 20) << 12) + (i2 & 4095)]);

    float4 oa, ob;
    oa.x = xa.x - ba.x; oa.y = xa.y - ba.y; oa.z = xa.z - ba.z; oa.w = xa.w - ba.w;
    ob.x = xb.x - bb.x; ob.y = xb.y - bb.y; ob.z = xb.z - bb.z; ob.w = xb.w - bb.w;
    out[i]  = oa;
    out[i2] = ob;
}

// ---------------------------------------------------------------------------
extern "C" void kernel_launch(void* const* d_in, const int* in_sizes, int n_in,
                              void* d_out, int out_size) {
    const float* x = (const float*)d_in[0];   // (16,256,128,128) fp32
    const float* f = (const float*)d_in[1];   // (3,3) fp32
    float* out = (float*)d_out;

    static float* part_ptr = nullptr;
    static float* s_ptr    = nullptr;
    static float* x1_ptr   = nullptr;
    if (part_ptr == nullptr) {
        cudaGetSymbolAddress((void**)&part_ptr, g_part);
        cudaGetSymbolAddress((void**)&s_ptr,    g_s);
        cudaGetSymbolAddress((void**)&x1_ptr,   g_x1);
    }

    // K1: partial channel sums (reads 256 MiB, 524288 threads)
    reduce_part_kernel<<<(CGROUPS * BHW4) / 256, 256>>>(
        (const float4*)x, (float4*)part_ptr);

    // K2a: combine partials -> s
    combine_kernel<<<BHW4 / 256, 256>>>((const float4*)part_ptr, (float4*)s_ptr);

    // K2b: conv3x3
    conv3_kernel<<<BHW / 256, 256>>>(s_ptr, f, x1_ptr);

    // K3: broadcast subtract (reads 256 MiB, writes 256 MiB)
    sub_kernel<<<(TOTAL4 / 2) / 256, 256>>>(
        (const float4*)x, (const float4*)x1_ptr, (float4*)out);
}